// round 1
// baseline (speedup 1.0000x reference)
#include <cuda_runtime.h>

// VisionDynamicSparseAttention: fp32 baseline pipeline
//  1) QKV GEMM (+bias, split into per-head Q(scaled)/K/V layouts)
//  2) Q@K^T per head -> g_attn
//  3) per-row exact 1024-th-largest threshold (radix select) + masked softmax (in-place)
//  4) P@V per head -> g_ctx in [B,S,H] layout
//  5) proj GEMM (+bias) -> d_out

namespace {
constexpr int NH    = 12;
constexpr int HDIM  = 64;
constexpr int BATCH = 2;
constexpr int SEQ   = 2048;
constexpr int HID   = 768;
constexpr int HEADS = BATCH * NH;   // 24
constexpr int KSEL  = 1024;         // tokens kept per row
}

// scratch (device globals: allocation-free per harness rules)
__device__ float g_q[HEADS * SEQ * HDIM];
__device__ float g_k[HEADS * SEQ * HDIM];
__device__ float g_v[HEADS * SEQ * HDIM];
__device__ float g_attn[(long long)HEADS * SEQ * SEQ];   // 402 MB
__device__ float g_ctx[BATCH * SEQ * HID];

// ---------------------------------------------------------------------------
// Generic 128x128 register-blocked SGEMM core: C = A[M,K] * B[N,K]^T
// 256 threads, each computes 8x8 via 4+4 split rows/cols (conflict-free LDS.128).
// Cfg provides A/B base pointers (device-side, so __device__ globals work) and
// the epilogue.
// ---------------------------------------------------------------------------
template <int K, class Cfg>
__global__ void __launch_bounds__(256) sgemm_nt(Cfg cfg) {
  __shared__ float As[16][128];
  __shared__ float Bs[16][128];

  const float* __restrict__ A = cfg.Aptr();
  const float* __restrict__ B = cfg.Bptr();

  const int tid = threadIdx.x;
  const int tx = tid & 15, ty = tid >> 4;
  const int m0 = blockIdx.y * 128;
  const int n0 = blockIdx.x * 128;
  const int lr = tid >> 2;            // 0..63
  const int lc = (tid & 3) << 2;      // 0,4,8,12

  float acc[8][8];
#pragma unroll
  for (int i = 0; i < 8; i++)
#pragma unroll
    for (int j = 0; j < 8; j++) acc[i][j] = 0.f;

#pragma unroll 1
  for (int k0 = 0; k0 < K; k0 += 16) {
    float4 a0 = *(const float4*)&A[(long)(m0 + lr) * K + k0 + lc];
    float4 a1 = *(const float4*)&A[(long)(m0 + lr + 64) * K + k0 + lc];
    float4 b0 = *(const float4*)&B[(long)(n0 + lr) * K + k0 + lc];
    float4 b1 = *(const float4*)&B[(long)(n0 + lr + 64) * K + k0 + lc];
    __syncthreads();
    As[lc + 0][lr] = a0.x; As[lc + 1][lr] = a0.y; As[lc + 2][lr] = a0.z; As[lc + 3][lr] = a0.w;
    As[lc + 0][lr + 64] = a1.x; As[lc + 1][lr + 64] = a1.y; As[lc + 2][lr + 64] = a1.z; As[lc + 3][lr + 64] = a1.w;
    Bs[lc + 0][lr] = b0.x; Bs[lc + 1][lr] = b0.y; Bs[lc + 2][lr] = b0.z; Bs[lc + 3][lr] = b0.w;
    Bs[lc + 0][lr + 64] = b1.x; Bs[lc + 1][lr + 64] = b1.y; Bs[lc + 2][lr + 64] = b1.z; Bs[lc + 3][lr + 64] = b1.w;
    __syncthreads();
#pragma unroll
    for (int kk = 0; kk < 16; kk++) {
      const float4* As4 = (const float4*)As[kk];
      const float4* Bs4 = (const float4*)Bs[kk];
      float4 aA = As4[ty], aB = As4[ty + 16];
      float4 bA = Bs4[tx], bB = Bs4[tx + 16];
      float am[8] = {aA.x, aA.y, aA.z, aA.w, aB.x, aB.y, aB.z, aB.w};
      float bn[8] = {bA.x, bA.y, bA.z, bA.w, bB.x, bB.y, bB.z, bB.w};
#pragma unroll
      for (int i = 0; i < 8; i++)
#pragma unroll
        for (int j = 0; j < 8; j++) acc[i][j] = fmaf(am[i], bn[j], acc[i][j]);
    }
  }
  cfg.epi(acc, m0, n0, tx, ty);
}

// row index helper for the 4+4 split: i<4 -> ty*4+i ; i>=4 -> 64+ty*4+(i-4)
__device__ __forceinline__ int split_idx(int base16, int i) {
  return (i < 4) ? base16 * 4 + i : 60 + base16 * 4 + i;
}

// ---------------- Stage 1: QKV GEMM ----------------
struct CfgQKV {
  const float* hid;
  const float* w;
  const float* bias;
  __device__ __forceinline__ const float* Aptr() const { return hid; }
  __device__ __forceinline__ const float* Bptr() const { return w; }
  __device__ __forceinline__ void epi(const float acc[8][8], int m0, int n0, int tx, int ty) const {
#pragma unroll
    for (int i = 0; i < 8; i++) {
      int m = m0 + split_idx(ty, i);
      int b = m >> 11, s = m & (SEQ - 1);
#pragma unroll
      for (int jg = 0; jg < 2; jg++) {
        int n = n0 + jg * 64 + tx * 4;
        int sec = n / HID;
        int rem = n - sec * HID;
        int h = rem >> 6, d = rem & 63;
        long base = ((long)((b * NH + h) * SEQ + s)) * HDIM + d;
        float4 v;
        v.x = acc[i][jg * 4 + 0] + bias[n + 0];
        v.y = acc[i][jg * 4 + 1] + bias[n + 1];
        v.z = acc[i][jg * 4 + 2] + bias[n + 2];
        v.w = acc[i][jg * 4 + 3] + bias[n + 3];
        if (sec == 0) {  // q: fold in softmax scale hd^-0.5 = 0.125
          v.x *= 0.125f; v.y *= 0.125f; v.z *= 0.125f; v.w *= 0.125f;
          *(float4*)&g_q[base] = v;
        } else if (sec == 1) {
          *(float4*)&g_k[base] = v;
        } else {
          *(float4*)&g_v[base] = v;
        }
      }
    }
  }
};

// ---------------- Stage 2: Q @ K^T per head ----------------
struct CfgQK {
  __device__ __forceinline__ const float* Aptr() const {
    return g_q + (long)blockIdx.z * SEQ * HDIM;
  }
  __device__ __forceinline__ const float* Bptr() const {
    return g_k + (long)blockIdx.z * SEQ * HDIM;
  }
  __device__ __forceinline__ void epi(const float acc[8][8], int m0, int n0, int tx, int ty) const {
    float* C = g_attn + (long long)blockIdx.z * SEQ * SEQ;
#pragma unroll
    for (int i = 0; i < 8; i++) {
      int m = m0 + split_idx(ty, i);
#pragma unroll
      for (int jg = 0; jg < 2; jg++) {
        int n = n0 + jg * 64 + tx * 4;
        float4 v = make_float4(acc[i][jg * 4 + 0], acc[i][jg * 4 + 1],
                               acc[i][jg * 4 + 2], acc[i][jg * 4 + 3]);
        *(float4*)&C[(long)m * SEQ + n] = v;
      }
    }
  }
};

// ---------------- Stage 5: output projection ----------------
struct CfgProj {
  const float* w;
  const float* bias;
  float* out;
  __device__ __forceinline__ const float* Aptr() const { return g_ctx; }
  __device__ __forceinline__ const float* Bptr() const { return w; }
  __device__ __forceinline__ void epi(const float acc[8][8], int m0, int n0, int tx, int ty) const {
#pragma unroll
    for (int i = 0; i < 8; i++) {
      int m = m0 + split_idx(ty, i);
#pragma unroll
      for (int jg = 0; jg < 2; jg++) {
        int n = n0 + jg * 64 + tx * 4;
        float4 v;
        v.x = acc[i][jg * 4 + 0] + bias[n + 0];
        v.y = acc[i][jg * 4 + 1] + bias[n + 1];
        v.z = acc[i][jg * 4 + 2] + bias[n + 2];
        v.w = acc[i][jg * 4 + 3] + bias[n + 3];
        *(float4*)&out[(long)m * HID + n] = v;
      }
    }
  }
};

// ---------------------------------------------------------------------------
// Stage 3: per-row exact 1024-th-largest threshold + masked softmax, in place.
// One 256-thread block per attention row (2048 scores, 8 per thread in regs).
// Radix select over order-preserving uint32 keys -> exact k-th largest value,
// then p = (v >= thr) ? exp(v - rowmax) : 0, normalized.
// ---------------------------------------------------------------------------
__global__ void __launch_bounds__(256) select_softmax_kernel() {
  float* row = g_attn + (long long)blockIdx.x * SEQ;
  __shared__ int hist[256];
  __shared__ float red[256];
  __shared__ unsigned s_prefix;
  __shared__ int s_r;
  const int tid = threadIdx.x;

  float4 va = *(const float4*)&row[tid * 8];
  float4 vb = *(const float4*)&row[tid * 8 + 4];
  float myv[8] = {va.x, va.y, va.z, va.w, vb.x, vb.y, vb.z, vb.w};

  float mx = myv[0];
#pragma unroll
  for (int i = 1; i < 8; i++) mx = fmaxf(mx, myv[i]);
  red[tid] = mx;
  if (tid == 0) { s_prefix = 0u; s_r = KSEL; }
  __syncthreads();
#pragma unroll
  for (int s = 128; s > 0; s >>= 1) {
    if (tid < s) red[tid] = fmaxf(red[tid], red[tid + s]);
    __syncthreads();
  }
  float rowmax = red[0];

  unsigned myu[8];
#pragma unroll
  for (int i = 0; i < 8; i++) {
    int b = __float_as_int(myv[i]);
    myu[i] = (unsigned)b ^ ((b < 0) ? 0xFFFFFFFFu : 0x80000000u);  // order-preserving
  }

  unsigned pmask = 0u;
  for (int shift = 24; shift >= 0; shift -= 8) {
    hist[tid] = 0;
    __syncthreads();
    unsigned prefix = s_prefix;
#pragma unroll
    for (int i = 0; i < 8; i++) {
      unsigned u = myu[i];
      if ((u & pmask) == prefix) atomicAdd(&hist[(u >> shift) & 0xFFu], 1);
    }
    __syncthreads();
    if (tid == 0) {
      int r = s_r, cum = 0, sel = 0;
      for (int bb = 255; bb >= 0; bb--) {
        cum += hist[bb];
        if (cum >= r) { sel = bb; break; }
      }
      s_r = r - (cum - hist[sel]);
      s_prefix = prefix | ((unsigned)sel << shift);
    }
    __syncthreads();
    pmask |= (0xFFu << shift);
  }
  unsigned thr = s_prefix;  // sortable key of exact 1024-th largest

  float myp[8];
  float esum = 0.f;
#pragma unroll
  for (int i = 0; i < 8; i++) {
    float e = (myu[i] >= thr) ? __expf(myv[i] - rowmax) : 0.f;
    myp[i] = e;
    esum += e;
  }
  red[tid] = esum;
  __syncthreads();
#pragma unroll
  for (int s = 128; s > 0; s >>= 1) {
    if (tid < s) red[tid] += red[tid + s];
    __syncthreads();
  }
  float inv = 1.f / red[0];

  float4 o0 = make_float4(myp[0] * inv, myp[1] * inv, myp[2] * inv, myp[3] * inv);
  float4 o1 = make_float4(myp[4] * inv, myp[5] * inv, myp[6] * inv, myp[7] * inv);
  *(float4*)&row[tid * 8] = o0;
  *(float4*)&row[tid * 8 + 4] = o1;
}

// ---------------------------------------------------------------------------
// Stage 4: C[2048,64] = P[2048,2048] @ V[2048,64] per head -> g_ctx [B,S,H]
// Block: 128 rows x 64 cols, 256 threads, 8x4 per thread, BK=32.
// ---------------------------------------------------------------------------
__global__ void __launch_bounds__(256) pv_gemm_kernel() {
  const int head = blockIdx.y;
  const int m0 = blockIdx.x * 128;
  const float* __restrict__ P = g_attn + (long long)head * SEQ * SEQ;
  const float* __restrict__ V = g_v + (long)head * SEQ * HDIM;
  __shared__ float Ps[32][128];
  __shared__ float Vs[32][64];
  const int tid = threadIdx.x;
  const int tx = tid & 15, ty = tid >> 4;

  float acc[8][4];
#pragma unroll
  for (int i = 0; i < 8; i++)
#pragma unroll
    for (int j = 0; j < 4; j++) acc[i][j] = 0.f;

#pragma unroll 1
  for (int k0 = 0; k0 < SEQ; k0 += 32) {
    float4 p[4], v[2];
#pragma unroll
    for (int l = 0; l < 4; l++) {
      int idx = tid + 256 * l;
      int r = idx >> 3, c = (idx & 7) << 2;
      p[l] = *(const float4*)&P[(long)(m0 + r) * SEQ + k0 + c];
    }
#pragma unroll
    for (int l = 0; l < 2; l++) {
      int idx = tid + 256 * l;
      int r = idx >> 4, c = (idx & 15) << 2;
      v[l] = *(const float4*)&V[(long)(k0 + r) * HDIM + c];
    }
    __syncthreads();
#pragma unroll
    for (int l = 0; l < 4; l++) {
      int idx = tid + 256 * l;
      int r = idx >> 3, c = (idx & 7) << 2;
      Ps[c + 0][r] = p[l].x; Ps[c + 1][r] = p[l].y; Ps[c + 2][r] = p[l].z; Ps[c + 3][r] = p[l].w;
    }
#pragma unroll
    for (int l = 0; l < 2; l++) {
      int idx = tid + 256 * l;
      int r = idx >> 4, c = (idx & 15) << 2;
      *(float4*)&Vs[r][c] = v[l];
    }
    __syncthreads();
#pragma unroll
    for (int kk = 0; kk < 32; kk++) {
      const float4* Ps4 = (const float4*)Ps[kk];
      float4 aA = Ps4[ty], aB = Ps4[ty + 16];
      float4 bv = *(const float4*)&Vs[kk][tx * 4];
      float am[8] = {aA.x, aA.y, aA.z, aA.w, aB.x, aB.y, aB.z, aB.w};
#pragma unroll
      for (int i = 0; i < 8; i++) {
        acc[i][0] = fmaf(am[i], bv.x, acc[i][0]);
        acc[i][1] = fmaf(am[i], bv.y, acc[i][1]);
        acc[i][2] = fmaf(am[i], bv.z, acc[i][2]);
        acc[i][3] = fmaf(am[i], bv.w, acc[i][3]);
      }
    }
  }

  const int b = head / NH, h = head - b * NH;
#pragma unroll
  for (int i = 0; i < 8; i++) {
    int m = m0 + split_idx(ty, i);
    float4 v = make_float4(acc[i][0], acc[i][1], acc[i][2], acc[i][3]);
    *(float4*)&g_ctx[(long)(b * SEQ + m) * HID + h * HDIM + tx * 4] = v;
  }
}

// ---------------------------------------------------------------------------
extern "C" void kernel_launch(void* const* d_in, const int* in_sizes, int n_in,
                              void* d_out, int out_size) {
  const float* hidden = (const float*)d_in[0];  // [2,2048,768]
  const float* qkv_w  = (const float*)d_in[1];  // [2304,768]
  const float* qkv_b  = (const float*)d_in[2];  // [2304]
  const float* proj_w = (const float*)d_in[3];  // [768,768]
  const float* proj_b = (const float*)d_in[4];  // [768]
  float* out = (float*)d_out;                   // [2,2048,768]

  // 1) QKV GEMM: M=4096, N=2304, K=768
  sgemm_nt<HID><<<dim3((3 * HID) / 128, (BATCH * SEQ) / 128, 1), 256>>>(
      CfgQKV{hidden, qkv_w, qkv_b});

  // 2) Q@K^T per head: M=N=2048, K=64, z=24
  sgemm_nt<HDIM><<<dim3(SEQ / 128, SEQ / 128, HEADS), 256>>>(CfgQK{});

  // 3) threshold + masked softmax, one block per row
  select_softmax_kernel<<<dim3(HEADS * SEQ), 256>>>();

  // 4) P@V per head
  pv_gemm_kernel<<<dim3(SEQ / 128, HEADS), 256>>>();

  // 5) projection: M=4096, N=768, K=768
  sgemm_nt<HID><<<dim3(HID / 128, (BATCH * SEQ) / 128, 1), 256>>>(
      CfgProj{proj_w, proj_b, out});
}

// round 2
// speedup vs baseline: 1.2309x; 1.2309x over previous
#include <cuda_runtime.h>
#include <cuda_fp16.h>
#include <cstdint>

// VisionDynamicSparseAttention pipeline (round 2):
//  1) QKV GEMM fp32 (+bias) -> Q(scaled)/K fp32, V fp16
//  2) Q@K^T per head fp32 -> g_attn (fp32 scores, exact selection)
//  3) per-row exact 1024-th-largest radix select + masked softmax -> g_p (fp16)
//  4) P@V per head via fp16 HMMA tensor cores -> g_ctx fp32 [B,S,H]
//  5) proj GEMM fp32 (+bias) -> d_out

namespace {
constexpr int NH    = 12;
constexpr int HDIM  = 64;
constexpr int BATCH = 2;
constexpr int SEQ   = 2048;
constexpr int HID   = 768;
constexpr int HEADS = BATCH * NH;   // 24
constexpr int KSEL  = 1024;
}

__device__ float  g_q[HEADS * SEQ * HDIM];
__device__ float  g_k[HEADS * SEQ * HDIM];
__device__ __half g_vh[HEADS * SEQ * HDIM];
__device__ float  g_attn[(long long)HEADS * SEQ * SEQ];   // fp32 scores, 402 MB
__device__ __half g_p[(long long)HEADS * SEQ * SEQ];      // fp16 probs, 201 MB
__device__ float  g_ctx[BATCH * SEQ * HID];

// ---------------------------------------------------------------------------
// Generic 128x128 register-blocked SGEMM core: C = A[M,K] * B[N,K]^T
// ---------------------------------------------------------------------------
template <int K, class Cfg>
__global__ void __launch_bounds__(256) sgemm_nt(Cfg cfg) {
  __shared__ float As[16][128];
  __shared__ float Bs[16][128];

  const float* __restrict__ A = cfg.Aptr();
  const float* __restrict__ B = cfg.Bptr();

  const int tid = threadIdx.x;
  const int tx = tid & 15, ty = tid >> 4;
  const int m0 = blockIdx.y * 128;
  const int n0 = blockIdx.x * 128;
  const int lr = tid >> 2;
  const int lc = (tid & 3) << 2;

  float acc[8][8];
#pragma unroll
  for (int i = 0; i < 8; i++)
#pragma unroll
    for (int j = 0; j < 8; j++) acc[i][j] = 0.f;

#pragma unroll 1
  for (int k0 = 0; k0 < K; k0 += 16) {
    float4 a0 = *(const float4*)&A[(long)(m0 + lr) * K + k0 + lc];
    float4 a1 = *(const float4*)&A[(long)(m0 + lr + 64) * K + k0 + lc];
    float4 b0 = *(const float4*)&B[(long)(n0 + lr) * K + k0 + lc];
    float4 b1 = *(const float4*)&B[(long)(n0 + lr + 64) * K + k0 + lc];
    __syncthreads();
    As[lc + 0][lr] = a0.x; As[lc + 1][lr] = a0.y; As[lc + 2][lr] = a0.z; As[lc + 3][lr] = a0.w;
    As[lc + 0][lr + 64] = a1.x; As[lc + 1][lr + 64] = a1.y; As[lc + 2][lr + 64] = a1.z; As[lc + 3][lr + 64] = a1.w;
    Bs[lc + 0][lr] = b0.x; Bs[lc + 1][lr] = b0.y; Bs[lc + 2][lr] = b0.z; Bs[lc + 3][lr] = b0.w;
    Bs[lc + 0][lr + 64] = b1.x; Bs[lc + 1][lr + 64] = b1.y; Bs[lc + 2][lr + 64] = b1.z; Bs[lc + 3][lr + 64] = b1.w;
    __syncthreads();
#pragma unroll
    for (int kk = 0; kk < 16; kk++) {
      const float4* As4 = (const float4*)As[kk];
      const float4* Bs4 = (const float4*)Bs[kk];
      float4 aA = As4[ty], aB = As4[ty + 16];
      float4 bA = Bs4[tx], bB = Bs4[tx + 16];
      float am[8] = {aA.x, aA.y, aA.z, aA.w, aB.x, aB.y, aB.z, aB.w};
      float bn[8] = {bA.x, bA.y, bA.z, bA.w, bB.x, bB.y, bB.z, bB.w};
#pragma unroll
      for (int i = 0; i < 8; i++)
#pragma unroll
        for (int j = 0; j < 8; j++) acc[i][j] = fmaf(am[i], bn[j], acc[i][j]);
    }
  }
  cfg.epi(acc, m0, n0, tx, ty);
}

__device__ __forceinline__ int split_idx(int base16, int i) {
  return (i < 4) ? base16 * 4 + i : 60 + base16 * 4 + i;
}

// ---------------- Stage 1: QKV GEMM ----------------
struct CfgQKV {
  const float* hid;
  const float* w;
  const float* bias;
  __device__ __forceinline__ const float* Aptr() const { return hid; }
  __device__ __forceinline__ const float* Bptr() const { return w; }
  __device__ __forceinline__ void epi(const float acc[8][8], int m0, int n0, int tx, int ty) const {
#pragma unroll
    for (int i = 0; i < 8; i++) {
      int m = m0 + split_idx(ty, i);
      int b = m >> 11, s = m & (SEQ - 1);
#pragma unroll
      for (int jg = 0; jg < 2; jg++) {
        int n = n0 + jg * 64 + tx * 4;
        int sec = n / HID;
        int rem = n - sec * HID;
        int h = rem >> 6, d = rem & 63;
        long base = ((long)((b * NH + h) * SEQ + s)) * HDIM + d;
        float4 v;
        v.x = acc[i][jg * 4 + 0] + bias[n + 0];
        v.y = acc[i][jg * 4 + 1] + bias[n + 1];
        v.z = acc[i][jg * 4 + 2] + bias[n + 2];
        v.w = acc[i][jg * 4 + 3] + bias[n + 3];
        if (sec == 0) {  // q: fold in softmax scale
          v.x *= 0.125f; v.y *= 0.125f; v.z *= 0.125f; v.w *= 0.125f;
          *(float4*)&g_q[base] = v;
        } else if (sec == 1) {
          *(float4*)&g_k[base] = v;
        } else {
          union { __half2 h[2]; uint2 u; } pk;
          pk.h[0] = __floats2half2_rn(v.x, v.y);
          pk.h[1] = __floats2half2_rn(v.z, v.w);
          *(uint2*)&g_vh[base] = pk.u;
        }
      }
    }
  }
};

// ---------------- Stage 2: Q @ K^T per head ----------------
struct CfgQK {
  __device__ __forceinline__ const float* Aptr() const {
    return g_q + (long)blockIdx.z * SEQ * HDIM;
  }
  __device__ __forceinline__ const float* Bptr() const {
    return g_k + (long)blockIdx.z * SEQ * HDIM;
  }
  __device__ __forceinline__ void epi(const float acc[8][8], int m0, int n0, int tx, int ty) const {
    float* C = g_attn + (long long)blockIdx.z * SEQ * SEQ;
#pragma unroll
    for (int i = 0; i < 8; i++) {
      int m = m0 + split_idx(ty, i);
#pragma unroll
      for (int jg = 0; jg < 2; jg++) {
        int n = n0 + jg * 64 + tx * 4;
        *(float4*)&C[(long)m * SEQ + n] = make_float4(
            acc[i][jg * 4 + 0], acc[i][jg * 4 + 1], acc[i][jg * 4 + 2], acc[i][jg * 4 + 3]);
      }
    }
  }
};

// ---------------- Stage 5: output projection ----------------
struct CfgProj {
  const float* w;
  const float* bias;
  float* out;
  __device__ __forceinline__ const float* Aptr() const { return g_ctx; }
  __device__ __forceinline__ const float* Bptr() const { return w; }
  __device__ __forceinline__ void epi(const float acc[8][8], int m0, int n0, int tx, int ty) const {
#pragma unroll
    for (int i = 0; i < 8; i++) {
      int m = m0 + split_idx(ty, i);
#pragma unroll
      for (int jg = 0; jg < 2; jg++) {
        int n = n0 + jg * 64 + tx * 4;
        float4 v;
        v.x = acc[i][jg * 4 + 0] + bias[n + 0];
        v.y = acc[i][jg * 4 + 1] + bias[n + 1];
        v.z = acc[i][jg * 4 + 2] + bias[n + 2];
        v.w = acc[i][jg * 4 + 3] + bias[n + 3];
        *(float4*)&out[(long)m * HID + n] = v;
      }
    }
  }
};

// ---------------------------------------------------------------------------
// Stage 3: exact radix select threshold + masked softmax; fp32 in, fp16 out.
// ---------------------------------------------------------------------------
__global__ void __launch_bounds__(256) select_softmax_kernel() {
  const float* row = g_attn + (long long)blockIdx.x * SEQ;
  __half* rowp = g_p + (long long)blockIdx.x * SEQ;
  __shared__ int hist[256];
  __shared__ float red[256];
  __shared__ unsigned s_prefix;
  __shared__ int s_r;
  const int tid = threadIdx.x;

  float4 va = *(const float4*)&row[tid * 8];
  float4 vb = *(const float4*)&row[tid * 8 + 4];
  float myv[8] = {va.x, va.y, va.z, va.w, vb.x, vb.y, vb.z, vb.w};

  float mx = myv[0];
#pragma unroll
  for (int i = 1; i < 8; i++) mx = fmaxf(mx, myv[i]);
  red[tid] = mx;
  if (tid == 0) { s_prefix = 0u; s_r = KSEL; }
  __syncthreads();
#pragma unroll
  for (int s = 128; s > 0; s >>= 1) {
    if (tid < s) red[tid] = fmaxf(red[tid], red[tid + s]);
    __syncthreads();
  }
  float rowmax = red[0];

  unsigned myu[8];
#pragma unroll
  for (int i = 0; i < 8; i++) {
    int b = __float_as_int(myv[i]);
    myu[i] = (unsigned)b ^ ((b < 0) ? 0xFFFFFFFFu : 0x80000000u);
  }

  unsigned pmask = 0u;
  for (int shift = 24; shift >= 0; shift -= 8) {
    hist[tid] = 0;
    __syncthreads();
    unsigned prefix = s_prefix;
#pragma unroll
    for (int i = 0; i < 8; i++) {
      unsigned u = myu[i];
      if ((u & pmask) == prefix) atomicAdd(&hist[(u >> shift) & 0xFFu], 1);
    }
    __syncthreads();
    if (tid == 0) {
      int r = s_r, cum = 0, sel = 0;
      for (int bb = 255; bb >= 0; bb--) {
        cum += hist[bb];
        if (cum >= r) { sel = bb; break; }
      }
      s_r = r - (cum - hist[sel]);
      s_prefix = prefix | ((unsigned)sel << shift);
    }
    __syncthreads();
    pmask |= (0xFFu << shift);
  }
  unsigned thr = s_prefix;

  float myp[8];
  float esum = 0.f;
#pragma unroll
  for (int i = 0; i < 8; i++) {
    float e = (myu[i] >= thr) ? __expf(myv[i] - rowmax) : 0.f;
    myp[i] = e;
    esum += e;
  }
  red[tid] = esum;
  __syncthreads();
#pragma unroll
  for (int s = 128; s > 0; s >>= 1) {
    if (tid < s) red[tid] += red[tid + s];
    __syncthreads();
  }
  float inv = 1.f / red[0];

  union { __half2 h[4]; uint4 u; } pk;
#pragma unroll
  for (int i = 0; i < 4; i++)
    pk.h[i] = __floats2half2_rn(myp[2 * i] * inv, myp[2 * i + 1] * inv);
  *(uint4*)&rowp[tid * 8] = pk.u;
}

// ---------------------------------------------------------------------------
// Stage 4: P@V per head with fp16 HMMA (mma.sync m16n8k16, fp32 accum).
// Block: 128 rows x 64 cols, 8 warps (each warp m16 x n64), BK=64.
// ---------------------------------------------------------------------------
__device__ __forceinline__ void ldsm_x4(uint32_t& r0, uint32_t& r1, uint32_t& r2,
                                        uint32_t& r3, uint32_t saddr) {
  asm volatile("ldmatrix.sync.aligned.m8n8.x4.shared.b16 {%0,%1,%2,%3}, [%4];"
               : "=r"(r0), "=r"(r1), "=r"(r2), "=r"(r3) : "r"(saddr));
}
__device__ __forceinline__ void ldsm_x4_t(uint32_t& r0, uint32_t& r1, uint32_t& r2,
                                          uint32_t& r3, uint32_t saddr) {
  asm volatile("ldmatrix.sync.aligned.m8n8.x4.trans.shared.b16 {%0,%1,%2,%3}, [%4];"
               : "=r"(r0), "=r"(r1), "=r"(r2), "=r"(r3) : "r"(saddr));
}
__device__ __forceinline__ void mma16816(float* c, uint32_t a0, uint32_t a1,
                                         uint32_t a2, uint32_t a3,
                                         uint32_t b0, uint32_t b1) {
  asm volatile(
      "mma.sync.aligned.m16n8k16.row.col.f32.f16.f16.f32 "
      "{%0,%1,%2,%3}, {%4,%5,%6,%7}, {%8,%9}, {%0,%1,%2,%3};"
      : "+f"(c[0]), "+f"(c[1]), "+f"(c[2]), "+f"(c[3])
      : "r"(a0), "r"(a1), "r"(a2), "r"(a3), "r"(b0), "r"(b1));
}

__global__ void __launch_bounds__(256) pv_hmma_kernel() {
  constexpr int LDP = 72;  // padded pitch (halves): 144B -> conflict-free ldmatrix
  __shared__ __half Ps[128 * LDP];
  __shared__ __half Vs[64 * LDP];

  const int head = blockIdx.y;
  const int m0 = blockIdx.x * 128;
  const __half* __restrict__ P = g_p + (long long)head * SEQ * SEQ;
  const __half* __restrict__ V = g_vh + (long)head * SEQ * HDIM;

  const int tid = threadIdx.x;
  const int warp = tid >> 5, lane = tid & 31;
  const int wm0 = warp * 16;

  float c[8][4];
#pragma unroll
  for (int i = 0; i < 8; i++)
#pragma unroll
    for (int j = 0; j < 4; j++) c[i][j] = 0.f;

  // loader indices: 8 int4 (=64 halves) per row
  const int pr = tid >> 3, pc = (tid & 7) << 3;   // P: rows tid/8 (+256/8 per step)
  const int vr = tid >> 3, vc = (tid & 7) << 3;   // V: same pattern, 64 rows in 2 steps

  int4 pregs[4], vregs[2];
#pragma unroll
  for (int l = 0; l < 4; l++)
    pregs[l] = *(const int4*)&P[(long)(m0 + pr + 32 * l) * SEQ + pc];
#pragma unroll
  for (int l = 0; l < 2; l++)
    vregs[l] = *(const int4*)&V[(long)(vr + 32 * l) * HDIM + vc];

  // precompute ldmatrix smem addresses (byte offsets advance per k-step)
  const uint32_t ps_base = (uint32_t)__cvta_generic_to_shared(Ps);
  const uint32_t vs_base = (uint32_t)__cvta_generic_to_shared(Vs);
  // A: row = wm0 + (lane&15), col = ks*16 + ((lane>>4)<<3)
  const uint32_t a_addr0 =
      ps_base + ((wm0 + (lane & 15)) * LDP + ((lane >> 4) << 3)) * 2;
  // B: k = ks*16 + (lane&7) + (lane&8), n = g*16 + ((lane&16)>>1)
  const uint32_t b_row = (lane & 7) + (lane & 8);
  const uint32_t b_addr0 = vs_base + (b_row * LDP + ((lane & 16) >> 1)) * 2;

#pragma unroll 1
  for (int it = 0; it < SEQ / 64; it++) {
    __syncthreads();
#pragma unroll
    for (int l = 0; l < 4; l++)
      *(int4*)&Ps[(pr + 32 * l) * LDP + pc] = pregs[l];
#pragma unroll
    for (int l = 0; l < 2; l++)
      *(int4*)&Vs[(vr + 32 * l) * LDP + vc] = vregs[l];
    __syncthreads();

    if (it + 1 < SEQ / 64) {
      int k0n = (it + 1) * 64;
#pragma unroll
      for (int l = 0; l < 4; l++)
        pregs[l] = *(const int4*)&P[(long)(m0 + pr + 32 * l) * SEQ + k0n + pc];
#pragma unroll
      for (int l = 0; l < 2; l++)
        vregs[l] = *(const int4*)&V[(long)(k0n + vr + 32 * l) * HDIM + vc];
    }

#pragma unroll
    for (int ks = 0; ks < 4; ks++) {
      uint32_t a0, a1, a2, a3;
      ldsm_x4(a0, a1, a2, a3, a_addr0 + ks * 16 * 2);
#pragma unroll
      for (int g = 0; g < 4; g++) {
        uint32_t b0, b1, b2, b3;
        ldsm_x4_t(b0, b1, b2, b3, b_addr0 + (ks * 16 * LDP + g * 16) * 2);
        mma16816(c[2 * g + 0], a0, a1, a2, a3, b0, b1);
        mma16816(c[2 * g + 1], a0, a1, a2, a3, b2, b3);
      }
    }
  }

  // epilogue -> g_ctx fp32 [B,S,H]
  const int b = head / NH, h = head - b * NH;
  const int r0 = lane >> 2, col0 = (lane & 3) * 2;
  const long rowbase0 = (long)(b * SEQ + m0 + wm0 + r0) * HID + h * HDIM;
  const long rowbase1 = rowbase0 + 8L * HID;
#pragma unroll
  for (int nt = 0; nt < 8; nt++) {
    int n = nt * 8 + col0;
    *(float2*)&g_ctx[rowbase0 + n] = make_float2(c[nt][0], c[nt][1]);
    *(float2*)&g_ctx[rowbase1 + n] = make_float2(c[nt][2], c[nt][3]);
  }
}

// ---------------------------------------------------------------------------
extern "C" void kernel_launch(void* const* d_in, const int* in_sizes, int n_in,
                              void* d_out, int out_size) {
  const float* hidden = (const float*)d_in[0];
  const float* qkv_w  = (const float*)d_in[1];
  const float* qkv_b  = (const float*)d_in[2];
  const float* proj_w = (const float*)d_in[3];
  const float* proj_b = (const float*)d_in[4];
  float* out = (float*)d_out;

  sgemm_nt<HID><<<dim3((3 * HID) / 128, (BATCH * SEQ) / 128, 1), 256>>>(
      CfgQKV{hidden, qkv_w, qkv_b});

  sgemm_nt<HDIM><<<dim3(SEQ / 128, SEQ / 128, HEADS), 256>>>(CfgQK{});

  select_softmax_kernel<<<dim3(HEADS * SEQ), 256>>>();

  pv_hmma_kernel<<<dim3(SEQ / 128, HEADS), 256>>>();

  sgemm_nt<HID><<<dim3(HID / 128, (BATCH * SEQ) / 128, 1), 256>>>(
      CfgProj{proj_w, proj_b, out});
}

// round 5
// speedup vs baseline: 1.4954x; 1.2149x over previous
#include <cuda_runtime.h>
#include <cuda_fp16.h>
#include <cstdint>

// VisionDynamicSparseAttention pipeline (round 5):
//  1) QKV GEMM fp32 (+bias) -> Q(scaled)/K as fp16 hi+lo splits, V fp16
//  2) Q@K^T via compensated fp16 HMMA (3 MMA phases) -> g_attn fp32 (exact-grade scores)
//  3) select: exact fp32 k-th largest (radix pass + warp bit-select) + masked softmax
//     (FMA exp2, no MUFU) -> g_p fp16
//  4) PV fp16 HMMA -> g_ctx fp32
//  5) proj GEMM fp32 (+bias) -> d_out

namespace {
constexpr int NH    = 12;
constexpr int HDIM  = 64;
constexpr int BATCH = 2;
constexpr int SEQ   = 2048;
constexpr int HID   = 768;
constexpr int HEADS = BATCH * NH;   // 24
constexpr int KSEL  = 1024;
constexpr float L2E = 1.4426950408889634f;
}

__device__ __half g_qh[HEADS * SEQ * HDIM];
__device__ __half g_ql[HEADS * SEQ * HDIM];
__device__ __half g_kh[HEADS * SEQ * HDIM];
__device__ __half g_kl[HEADS * SEQ * HDIM];
__device__ __half g_vh[HEADS * SEQ * HDIM];
__device__ float  g_attn[(long long)HEADS * SEQ * SEQ];  // fp32 scores, 402 MB
__device__ __half g_p[(long long)HEADS * SEQ * SEQ];     // fp16 probs, 201 MB
__device__ float  g_ctx[BATCH * SEQ * HID];

// FMA-only exp2 (range-reduced deg-5; rel err ~2.4e-6)
__device__ __forceinline__ float fast_exp2(float y) {
  float t = y + 12582912.0f;
  int   i = __float_as_int(t);
  float f = y - (t - 12582912.0f);
  float p = 1.3333558146e-3f;
  p = fmaf(p, f, 9.6181291918e-3f);
  p = fmaf(p, f, 5.5504108665e-2f);
  p = fmaf(p, f, 2.4022650696e-1f);
  p = fmaf(p, f, 6.9314718056e-1f);
  p = fmaf(p, f, 1.0f);
  return __int_as_float(__float_as_int(p) + (i << 23));
}

// ---------------------------------------------------------------------------
// fp32 SGEMM core (stages 1 & 5): C = A[M,K] * B[N,K]^T
// ---------------------------------------------------------------------------
template <int K, class Cfg>
__global__ void __launch_bounds__(256) sgemm_nt(Cfg cfg) {
  __shared__ float As[16][128];
  __shared__ float Bs[16][128];

  const float* __restrict__ A = cfg.Aptr();
  const float* __restrict__ B = cfg.Bptr();

  const int tid = threadIdx.x;
  const int tx = tid & 15, ty = tid >> 4;
  const int m0 = blockIdx.y * 128;
  const int n0 = blockIdx.x * 128;
  const int lr = tid >> 2;
  const int lc = (tid & 3) << 2;

  float acc[8][8];
#pragma unroll
  for (int i = 0; i < 8; i++)
#pragma unroll
    for (int j = 0; j < 8; j++) acc[i][j] = 0.f;

#pragma unroll 1
  for (int k0 = 0; k0 < K; k0 += 16) {
    float4 a0 = *(const float4*)&A[(long)(m0 + lr) * K + k0 + lc];
    float4 a1 = *(const float4*)&A[(long)(m0 + lr + 64) * K + k0 + lc];
    float4 b0 = *(const float4*)&B[(long)(n0 + lr) * K + k0 + lc];
    float4 b1 = *(const float4*)&B[(long)(n0 + lr + 64) * K + k0 + lc];
    __syncthreads();
    As[lc + 0][lr] = a0.x; As[lc + 1][lr] = a0.y; As[lc + 2][lr] = a0.z; As[lc + 3][lr] = a0.w;
    As[lc + 0][lr + 64] = a1.x; As[lc + 1][lr + 64] = a1.y; As[lc + 2][lr + 64] = a1.z; As[lc + 3][lr + 64] = a1.w;
    Bs[lc + 0][lr] = b0.x; Bs[lc + 1][lr] = b0.y; Bs[lc + 2][lr] = b0.z; Bs[lc + 3][lr] = b0.w;
    Bs[lc + 0][lr + 64] = b1.x; Bs[lc + 1][lr + 64] = b1.y; Bs[lc + 2][lr + 64] = b1.z; Bs[lc + 3][lr + 64] = b1.w;
    __syncthreads();
#pragma unroll
    for (int kk = 0; kk < 16; kk++) {
      const float4* As4 = (const float4*)As[kk];
      const float4* Bs4 = (const float4*)Bs[kk];
      float4 aA = As4[ty], aB = As4[ty + 16];
      float4 bA = Bs4[tx], bB = Bs4[tx + 16];
      float am[8] = {aA.x, aA.y, aA.z, aA.w, aB.x, aB.y, aB.z, aB.w};
      float bn[8] = {bA.x, bA.y, bA.z, bA.w, bB.x, bB.y, bB.z, bB.w};
#pragma unroll
      for (int i = 0; i < 8; i++)
#pragma unroll
        for (int j = 0; j < 8; j++) acc[i][j] = fmaf(am[i], bn[j], acc[i][j]);
    }
  }
  cfg.epi(acc, m0, n0, tx, ty);
}

__device__ __forceinline__ int split_idx(int base16, int i) {
  return (i < 4) ? base16 * 4 + i : 60 + base16 * 4 + i;
}

__device__ __forceinline__ uint2 split_pack4(float4 v, uint2& lo) {
  union { __half2 h2[2]; uint2 u; } hi, lw;
  __half hx = __float2half_rn(v.x), hy = __float2half_rn(v.y);
  __half hz = __float2half_rn(v.z), hw = __float2half_rn(v.w);
  hi.h2[0] = __halves2half2(hx, hy);
  hi.h2[1] = __halves2half2(hz, hw);
  lw.h2[0] = __floats2half2_rn(v.x - __half2float(hx), v.y - __half2float(hy));
  lw.h2[1] = __floats2half2_rn(v.z - __half2float(hz), v.w - __half2float(hw));
  lo = lw.u;
  return hi.u;
}

// ---------------- Stage 1: QKV GEMM (epilogue -> fp16 splits) ----------------
struct CfgQKV {
  const float* hid;
  const float* w;
  const float* bias;
  __device__ __forceinline__ const float* Aptr() const { return hid; }
  __device__ __forceinline__ const float* Bptr() const { return w; }
  __device__ __forceinline__ void epi(const float acc[8][8], int m0, int n0, int tx, int ty) const {
#pragma unroll
    for (int i = 0; i < 8; i++) {
      int m = m0 + split_idx(ty, i);
      int b = m >> 11, s = m & (SEQ - 1);
#pragma unroll
      for (int jg = 0; jg < 2; jg++) {
        int n = n0 + jg * 64 + tx * 4;
        int sec = n / HID;
        int rem = n - sec * HID;
        int h = rem >> 6, d = rem & 63;
        long base = ((long)((b * NH + h) * SEQ + s)) * HDIM + d;
        float4 v;
        v.x = acc[i][jg * 4 + 0] + bias[n + 0];
        v.y = acc[i][jg * 4 + 1] + bias[n + 1];
        v.z = acc[i][jg * 4 + 2] + bias[n + 2];
        v.w = acc[i][jg * 4 + 3] + bias[n + 3];
        if (sec == 0) {  // q, softmax scale folded in
          v.x *= 0.125f; v.y *= 0.125f; v.z *= 0.125f; v.w *= 0.125f;
          uint2 lo;
          uint2 hi = split_pack4(v, lo);
          *(uint2*)&g_qh[base] = hi;
          *(uint2*)&g_ql[base] = lo;
        } else if (sec == 1) {
          uint2 lo;
          uint2 hi = split_pack4(v, lo);
          *(uint2*)&g_kh[base] = hi;
          *(uint2*)&g_kl[base] = lo;
        } else {
          union { __half2 h2[2]; uint2 u; } pk;
          pk.h2[0] = __floats2half2_rn(v.x, v.y);
          pk.h2[1] = __floats2half2_rn(v.z, v.w);
          *(uint2*)&g_vh[base] = pk.u;
        }
      }
    }
  }
};

// ---------------- Stage 5: output projection ----------------
struct CfgProj {
  const float* w;
  const float* bias;
  float* out;
  __device__ __forceinline__ const float* Aptr() const { return g_ctx; }
  __device__ __forceinline__ const float* Bptr() const { return w; }
  __device__ __forceinline__ void epi(const float acc[8][8], int m0, int n0, int tx, int ty) const {
#pragma unroll
    for (int i = 0; i < 8; i++) {
      int m = m0 + split_idx(ty, i);
#pragma unroll
      for (int jg = 0; jg < 2; jg++) {
        int n = n0 + jg * 64 + tx * 4;
        float4 v;
        v.x = acc[i][jg * 4 + 0] + bias[n + 0];
        v.y = acc[i][jg * 4 + 1] + bias[n + 1];
        v.z = acc[i][jg * 4 + 2] + bias[n + 2];
        v.w = acc[i][jg * 4 + 3] + bias[n + 3];
        *(float4*)&out[(long)m * HID + n] = v;
      }
    }
  }
};

// ---------------------------------------------------------------------------
// HMMA primitives
// ---------------------------------------------------------------------------
__device__ __forceinline__ void ldsm_x4(uint32_t& r0, uint32_t& r1, uint32_t& r2,
                                        uint32_t& r3, uint32_t saddr) {
  asm volatile("ldmatrix.sync.aligned.m8n8.x4.shared.b16 {%0,%1,%2,%3}, [%4];"
               : "=r"(r0), "=r"(r1), "=r"(r2), "=r"(r3) : "r"(saddr));
}
__device__ __forceinline__ void ldsm_x4_t(uint32_t& r0, uint32_t& r1, uint32_t& r2,
                                          uint32_t& r3, uint32_t saddr) {
  asm volatile("ldmatrix.sync.aligned.m8n8.x4.trans.shared.b16 {%0,%1,%2,%3}, [%4];"
               : "=r"(r0), "=r"(r1), "=r"(r2), "=r"(r3) : "r"(saddr));
}
__device__ __forceinline__ void mma16816(float* c, uint32_t a0, uint32_t a1,
                                         uint32_t a2, uint32_t a3,
                                         uint32_t b0, uint32_t b1) {
  asm volatile(
      "mma.sync.aligned.m16n8k16.row.col.f32.f16.f16.f32 "
      "{%0,%1,%2,%3}, {%4,%5,%6,%7}, {%8,%9}, {%0,%1,%2,%3};"
      : "+f"(c[0]), "+f"(c[1]), "+f"(c[2]), "+f"(c[3])
      : "r"(a0), "r"(a1), "r"(a2), "r"(a3), "r"(b0), "r"(b1));
}

// ---------------------------------------------------------------------------
// Stage 2: compensated QK^T per head -> fp32 scores.
// 128x128 tile, K=64. Phases: (Qh,Kh), (Qh,Kl), (Ql,Kh reload). 8 warps.
// ---------------------------------------------------------------------------
__global__ void __launch_bounds__(256) qk_comp_kernel() {
  constexpr int LDQ = 72;   // halves, 144B rows: ldmatrix conflict-free
  __shared__ __align__(16) __half smem_qk[2 * 128 * LDQ];  // 36864 B
  __half* Qs = smem_qk;
  __half* Ks = smem_qk + 128 * LDQ;

  const int head = blockIdx.z;
  const int m0 = blockIdx.y * 128;
  const int n0 = blockIdx.x * 128;
  const long qoff = (long)head * SEQ * HDIM;

  const int tid = threadIdx.x;
  const int warp = tid >> 5, lane = tid & 31;
  const int warp_m = warp >> 1, warp_n = warp & 1;

  const int lrow = tid >> 1;
  const int lcol = (tid & 1) * 32;

  float c[2][8][4];
#pragma unroll
  for (int mi = 0; mi < 2; mi++)
#pragma unroll
    for (int ni = 0; ni < 8; ni++)
#pragma unroll
      for (int j = 0; j < 4; j++) c[mi][ni][j] = 0.f;

  const uint32_t qs_b = (uint32_t)__cvta_generic_to_shared(Qs);
  const uint32_t ks_b = (uint32_t)__cvta_generic_to_shared(Ks);
  const uint32_t a_off = ((warp_m * 32 + (lane & 15)) * LDQ + ((lane >> 4) << 3)) * 2;
  const uint32_t b_off = ((warp_n * 64 + (lane & 15)) * LDQ + ((lane >> 4) << 3)) * 2;

  const __half* qsrc[3] = {g_qh + qoff, g_qh + qoff, g_ql + qoff};
  const __half* ksrc[3] = {g_kh + qoff, g_kl + qoff, g_kh + qoff};

#pragma unroll 1
  for (int ph = 0; ph < 3; ph++) {
    const bool load_q = (ph != 1);
    const __half* Qg = qsrc[ph];
    const __half* Kg = ksrc[ph];
    __syncthreads();
    if (load_q) {
#pragma unroll
      for (int i = 0; i < 4; i++)
        *(int4*)&Qs[lrow * LDQ + lcol + i * 8] =
            *(const int4*)&Qg[(long)(m0 + lrow) * HDIM + lcol + i * 8];
    }
#pragma unroll
    for (int i = 0; i < 4; i++)
      *(int4*)&Ks[lrow * LDQ + lcol + i * 8] =
          *(const int4*)&Kg[(long)(n0 + lrow) * HDIM + lcol + i * 8];
    __syncthreads();

#pragma unroll
    for (int ks = 0; ks < 4; ks++) {
      uint32_t a[2][4];
#pragma unroll
      for (int mi = 0; mi < 2; mi++)
        ldsm_x4(a[mi][0], a[mi][1], a[mi][2], a[mi][3],
                qs_b + a_off + (mi * 16 * LDQ + ks * 16) * 2);
#pragma unroll
      for (int nig = 0; nig < 4; nig++) {
        uint32_t b0, b1, b2, b3;
        ldsm_x4(b0, b1, b2, b3, ks_b + b_off + (nig * 16 * LDQ + ks * 16) * 2);
#pragma unroll
        for (int mi = 0; mi < 2; mi++) {
          mma16816(c[mi][2 * nig + 0], a[mi][0], a[mi][1], a[mi][2], a[mi][3], b0, b2);
          mma16816(c[mi][2 * nig + 1], a[mi][0], a[mi][1], a[mi][2], a[mi][3], b1, b3);
        }
      }
    }
  }

  // direct fp32 stores (32B segments per 8-col fragment row)
  float* C = g_attn + (long long)head * SEQ * SEQ;
#pragma unroll
  for (int mi = 0; mi < 2; mi++) {
    const int r = m0 + warp_m * 32 + mi * 16 + (lane >> 2);
#pragma unroll
    for (int ni = 0; ni < 8; ni++) {
      const int col = n0 + warp_n * 64 + ni * 8 + 2 * (lane & 3);
      *(float2*)&C[(long)r * SEQ + col] = make_float2(c[mi][ni][0], c[mi][ni][1]);
      *(float2*)&C[(long)(r + 8) * SEQ + col] = make_float2(c[mi][ni][2], c[mi][ni][3]);
    }
  }
}

// ---------------------------------------------------------------------------
// Stage 3: exact fp32 k-th largest + masked softmax -> fp16 P.
// One 256-thread block per row. Radix pass on high byte (parallel suffix scan),
// gather candidates, single-warp 24-bit bitwise select, FMA exp2, normalize.
// ---------------------------------------------------------------------------
__global__ void __launch_bounds__(256) select_softmax_kernel() {
  const float* row = g_attn + (long long)blockIdx.x * SEQ;
  __half* rowp = g_p + (long long)blockIdx.x * SEQ;

  __shared__ int hist[256];
  __shared__ int scan[256];
  __shared__ float redf[8];
  __shared__ float s_max, s_inv;
  __shared__ int s_bucket, s_r, s_cnt;
  __shared__ unsigned s_thr;
  __shared__ unsigned cand[2048];

  const int tid = threadIdx.x;
  const int warp = tid >> 5, lane = tid & 31;

  float4 va = *(const float4*)&row[tid * 8];
  float4 vb = *(const float4*)&row[tid * 8 + 4];
  float myv[8] = {va.x, va.y, va.z, va.w, vb.x, vb.y, vb.z, vb.w};

  // row max: warp shuffle + cross-warp
  float mx = myv[0];
#pragma unroll
  for (int i = 1; i < 8; i++) mx = fmaxf(mx, myv[i]);
#pragma unroll
  for (int o = 16; o > 0; o >>= 1) mx = fmaxf(mx, __shfl_xor_sync(~0u, mx, o));
  if (lane == 0) redf[warp] = mx;
  hist[tid] = 0;  // also init histogram (before the same barrier)
  __syncthreads();
  if (warp == 0) {
    float m2 = (lane < 8) ? redf[lane] : -3.4e38f;
#pragma unroll
    for (int o = 4; o > 0; o >>= 1) m2 = fmaxf(m2, __shfl_xor_sync(~0u, m2, o));
    if (lane == 0) s_max = m2;
  }

  // sortable keys
  unsigned key[8];
#pragma unroll
  for (int i = 0; i < 8; i++) {
    int b = __float_as_int(myv[i]);
    key[i] = (unsigned)b ^ ((b < 0) ? 0xFFFFFFFFu : 0x80000000u);
  }

  // histogram on high byte
#pragma unroll
  for (int i = 0; i < 8; i++) atomicAdd(&hist[key[i] >> 24], 1);
  __syncthreads();

  // parallel suffix scan (Hillis-Steele)
  scan[tid] = hist[tid];
  __syncthreads();
#pragma unroll
  for (int off = 1; off < 256; off <<= 1) {
    int t = scan[tid] + ((tid + off < 256) ? scan[tid + off] : 0);
    __syncthreads();
    scan[tid] = t;
    __syncthreads();
  }
  // bucket containing the KSEL-th largest
  if (scan[tid] >= KSEL && (tid == 255 || scan[tid + 1] < KSEL)) {
    s_bucket = tid;
    s_r = KSEL - ((tid == 255) ? 0 : scan[tid + 1]);
    s_cnt = 0;
  }
  __syncthreads();
  const unsigned bucket = (unsigned)s_bucket;

  // gather candidates with matching high byte
#pragma unroll
  for (int i = 0; i < 8; i++)
    if ((key[i] >> 24) == bucket) cand[atomicAdd(&s_cnt, 1)] = key[i];
  __syncthreads();

  // warp 0: bitwise select of r-th largest among candidates (low 24 bits)
  if (warp == 0) {
    const int c = s_cnt;
    int r = s_r;
    unsigned P = bucket << 24;
#pragma unroll 1
    for (int b = 23; b >= 0; b--) {
      const unsigned want = (P | (1u << b)) >> b;
      int cnt = 0;
      for (int i = lane; i < c; i += 32)
        if ((cand[i] >> b) == want) cnt++;
#pragma unroll
      for (int o = 16; o > 0; o >>= 1) cnt += __shfl_xor_sync(~0u, cnt, o);
      if (r <= cnt) P |= 1u << b;
      else r -= cnt;
    }
    if (lane == 0) s_thr = P;
  }
  __syncthreads();
  const unsigned thr = s_thr;
  const float rowmax = s_max;

  // masked exp (FMA-only) + sum
  const float nm = -rowmax * L2E;
  float myp[8];
  float esum = 0.f;
#pragma unroll
  for (int i = 0; i < 8; i++) {
    float e = (key[i] >= thr) ? fast_exp2(fmaf(myv[i], L2E, nm)) : 0.f;
    myp[i] = e;
    esum += e;
  }
#pragma unroll
  for (int o = 16; o > 0; o >>= 1) esum += __shfl_xor_sync(~0u, esum, o);
  if (lane == 0) redf[warp] = esum;
  __syncthreads();
  if (warp == 0) {
    float z = (lane < 8) ? redf[lane] : 0.f;
#pragma unroll
    for (int o = 4; o > 0; o >>= 1) z += __shfl_xor_sync(~0u, z, o);
    if (lane == 0) s_inv = 1.f / z;
  }
  __syncthreads();
  const float inv = s_inv;

  union { __half2 h[4]; uint4 u; } pk;
#pragma unroll
  for (int i = 0; i < 4; i++)
    pk.h[i] = __floats2half2_rn(myp[2 * i] * inv, myp[2 * i + 1] * inv);
  *(uint4*)&rowp[tid * 8] = pk.u;
}

// ---------------------------------------------------------------------------
// Stage 4: P@V per head with fp16 HMMA (R2-proven).
// Block: 128 rows x 64 cols, 8 warps (m16 each), BK=64.
// ---------------------------------------------------------------------------
__global__ void __launch_bounds__(256) pv_hmma_kernel() {
  constexpr int LDP = 72;
  __shared__ __half Ps[128 * LDP];
  __shared__ __half Vs[64 * LDP];

  const int head = blockIdx.y;
  const int m0 = blockIdx.x * 128;
  const __half* __restrict__ P = g_p + (long long)head * SEQ * SEQ;
  const __half* __restrict__ V = g_vh + (long)head * SEQ * HDIM;

  const int tid = threadIdx.x;
  const int warp = tid >> 5, lane = tid & 31;
  const int wm0 = warp * 16;

  float c[8][4];
#pragma unroll
  for (int i = 0; i < 8; i++)
#pragma unroll
    for (int j = 0; j < 4; j++) c[i][j] = 0.f;

  const int pr = tid >> 3, pc = (tid & 7) << 3;
  const int vr = tid >> 3, vc = (tid & 7) << 3;

  int4 pregs[4], vregs[2];
#pragma unroll
  for (int l = 0; l < 4; l++)
    pregs[l] = *(const int4*)&P[(long)(m0 + pr + 32 * l) * SEQ + pc];
#pragma unroll
  for (int l = 0; l < 2; l++)
    vregs[l] = *(const int4*)&V[(long)(vr + 32 * l) * HDIM + vc];

  const uint32_t ps_base = (uint32_t)__cvta_generic_to_shared(Ps);
  const uint32_t vs_base = (uint32_t)__cvta_generic_to_shared(Vs);
  const uint32_t a_addr0 =
      ps_base + ((wm0 + (lane & 15)) * LDP + ((lane >> 4) << 3)) * 2;
  const uint32_t b_row = (lane & 7) + (lane & 8);
  const uint32_t b_addr0 = vs_base + (b_row * LDP + ((lane & 16) >> 1)) * 2;

#pragma unroll 1
  for (int it = 0; it < SEQ / 64; it++) {
    __syncthreads();
#pragma unroll
    for (int l = 0; l < 4; l++)
      *(int4*)&Ps[(pr + 32 * l) * LDP + pc] = pregs[l];
#pragma unroll
    for (int l = 0; l < 2; l++)
      *(int4*)&Vs[(vr + 32 * l) * LDP + vc] = vregs[l];
    __syncthreads();

    if (it + 1 < SEQ / 64) {
      int k0n = (it + 1) * 64;
#pragma unroll
      for (int l = 0; l < 4; l++)
        pregs[l] = *(const int4*)&P[(long)(m0 + pr + 32 * l) * SEQ + k0n + pc];
#pragma unroll
      for (int l = 0; l < 2; l++)
        vregs[l] = *(const int4*)&V[(long)(k0n + vr + 32 * l) * HDIM + vc];
    }

#pragma unroll
    for (int ks = 0; ks < 4; ks++) {
      uint32_t a0, a1, a2, a3;
      ldsm_x4(a0, a1, a2, a3, a_addr0 + ks * 16 * 2);
#pragma unroll
      for (int g = 0; g < 4; g++) {
        uint32_t b0, b1, b2, b3;
        ldsm_x4_t(b0, b1, b2, b3, b_addr0 + (ks * 16 * LDP + g * 16) * 2);
        mma16816(c[2 * g + 0], a0, a1, a2, a3, b0, b1);
        mma16816(c[2 * g + 1], a0, a1, a2, a3, b2, b3);
      }
    }
  }

  const int b = head / NH, h = head - b * NH;
  const int r0 = lane >> 2, col0 = (lane & 3) * 2;
  const long rowbase0 = (long)(b * SEQ + m0 + wm0 + r0) * HID + h * HDIM;
  const long rowbase1 = rowbase0 + 8L * HID;
#pragma unroll
  for (int nt = 0; nt < 8; nt++) {
    int n = nt * 8 + col0;
    *(float2*)&g_ctx[rowbase0 + n] = make_float2(c[nt][0], c[nt][1]);
    *(float2*)&g_ctx[rowbase1 + n] = make_float2(c[nt][2], c[nt][3]);
  }
}

// ---------------------------------------------------------------------------
extern "C" void kernel_launch(void* const* d_in, const int* in_sizes, int n_in,
                              void* d_out, int out_size) {
  const float* hidden = (const float*)d_in[0];
  const float* qkv_w  = (const float*)d_in[1];
  const float* qkv_b  = (const float*)d_in[2];
  const float* proj_w = (const float*)d_in[3];
  const float* proj_b = (const float*)d_in[4];
  float* out = (float*)d_out;

  sgemm_nt<HID><<<dim3((3 * HID) / 128, (BATCH * SEQ) / 128, 1), 256>>>(
      CfgQKV{hidden, qkv_w, qkv_b});

  qk_comp_kernel<<<dim3(SEQ / 128, SEQ / 128, HEADS), 256>>>();

  select_softmax_kernel<<<dim3(HEADS * SEQ), 256>>>();

  pv_hmma_kernel<<<dim3(SEQ / 128, HEADS), 256>>>();

  sgemm_nt<HID><<<dim3(HID / 128, (BATCH * SEQ) / 128, 1), 256>>>(
      CfgProj{proj_w, proj_b, out});
}

// round 6
// speedup vs baseline: 1.7472x; 1.1683x over previous
#include <cuda_runtime.h>
#include <cuda_fp16.h>
#include <cstdint>

// VisionDynamicSparseAttention pipeline (round 6):
//  0) split kernels: hidden/qkv_w/proj_w -> fp16 hi+lo pairs
//  1) QKV via compensated fp16 HMMA (+bias) -> Q(scaled)/K hi+lo fp16, V fp16
//  2) Q@K^T via compensated fp16 HMMA -> g_attn fp32 (exact-grade scores)
//  3) select: exact fp32 k-th largest + masked softmax (FMA exp2) -> g_p fp16
//  4) PV fp16 HMMA -> ctx as fp16 hi+lo
//  5) proj via compensated fp16 HMMA (+bias) -> d_out fp32

namespace {
constexpr int NH    = 12;
constexpr int HDIM  = 64;
constexpr int BATCH = 2;
constexpr int SEQ   = 2048;
constexpr int HID   = 768;
constexpr int HEADS = BATCH * NH;   // 24
constexpr int KSEL  = 1024;
constexpr float L2E = 1.4426950408889634f;
}

// fp16 hi/lo operand copies
__device__ __half g_hidh[BATCH * SEQ * HID];
__device__ __half g_hidl[BATCH * SEQ * HID];
__device__ __half g_wqh[3 * HID * HID];
__device__ __half g_wql[3 * HID * HID];
__device__ __half g_wph[HID * HID];
__device__ __half g_wpl[HID * HID];
// per-head q/k (hi+lo), v
__device__ __half g_qh[HEADS * SEQ * HDIM];
__device__ __half g_ql[HEADS * SEQ * HDIM];
__device__ __half g_kh[HEADS * SEQ * HDIM];
__device__ __half g_kl[HEADS * SEQ * HDIM];
__device__ __half g_vh[HEADS * SEQ * HDIM];
// attention
__device__ float  g_attn[(long long)HEADS * SEQ * SEQ];  // fp32 scores, 402 MB
__device__ __half g_p[(long long)HEADS * SEQ * SEQ];     // fp16 probs, 201 MB
// context (hi+lo for proj A operand)
__device__ __half g_ctxh[BATCH * SEQ * HID];
__device__ __half g_ctxl[BATCH * SEQ * HID];

// FMA-only exp2 (range-reduced deg-5; rel err ~2.4e-6)
__device__ __forceinline__ float fast_exp2(float y) {
  float t = y + 12582912.0f;
  int   i = __float_as_int(t);
  float f = y - (t - 12582912.0f);
  float p = 1.3333558146e-3f;
  p = fmaf(p, f, 9.6181291918e-3f);
  p = fmaf(p, f, 5.5504108665e-2f);
  p = fmaf(p, f, 2.4022650696e-1f);
  p = fmaf(p, f, 6.9314718056e-1f);
  p = fmaf(p, f, 1.0f);
  return __int_as_float(__float_as_int(p) + (i << 23));
}

// ---------------------------------------------------------------------------
// split: fp32 -> fp16 hi + lo residual (vectorized, grid-stride-free)
// ---------------------------------------------------------------------------
__global__ void __launch_bounds__(256) split_kernel(const float* __restrict__ src,
                                                    __half* __restrict__ hi,
                                                    __half* __restrict__ lo, int n4) {
  int i = blockIdx.x * blockDim.x + threadIdx.x;
  if (i >= n4) return;
  float4 v = ((const float4*)src)[i];
  __half hx = __float2half_rn(v.x), hy = __float2half_rn(v.y);
  __half hz = __float2half_rn(v.z), hw = __float2half_rn(v.w);
  union { __half2 h2[2]; uint2 u; } H, L;
  H.h2[0] = __halves2half2(hx, hy);
  H.h2[1] = __halves2half2(hz, hw);
  L.h2[0] = __floats2half2_rn(v.x - __half2float(hx), v.y - __half2float(hy));
  L.h2[1] = __floats2half2_rn(v.z - __half2float(hz), v.w - __half2float(hw));
  ((uint2*)hi)[i] = H.u;
  ((uint2*)lo)[i] = L.u;
}

// ---------------------------------------------------------------------------
// HMMA primitives
// ---------------------------------------------------------------------------
__device__ __forceinline__ void ldsm_x4(uint32_t& r0, uint32_t& r1, uint32_t& r2,
                                        uint32_t& r3, uint32_t saddr) {
  asm volatile("ldmatrix.sync.aligned.m8n8.x4.shared.b16 {%0,%1,%2,%3}, [%4];"
               : "=r"(r0), "=r"(r1), "=r"(r2), "=r"(r3) : "r"(saddr));
}
__device__ __forceinline__ void ldsm_x4_t(uint32_t& r0, uint32_t& r1, uint32_t& r2,
                                          uint32_t& r3, uint32_t saddr) {
  asm volatile("ldmatrix.sync.aligned.m8n8.x4.trans.shared.b16 {%0,%1,%2,%3}, [%4];"
               : "=r"(r0), "=r"(r1), "=r"(r2), "=r"(r3) : "r"(saddr));
}
__device__ __forceinline__ void mma16816(float* c, const uint32_t a[4],
                                         uint32_t b0, uint32_t b1) {
  asm volatile(
      "mma.sync.aligned.m16n8k16.row.col.f32.f16.f16.f32 "
      "{%0,%1,%2,%3}, {%4,%5,%6,%7}, {%8,%9}, {%0,%1,%2,%3};"
      : "+f"(c[0]), "+f"(c[1]), "+f"(c[2]), "+f"(c[3])
      : "r"(a[0]), "r"(a[1]), "r"(a[2]), "r"(a[3]), "r"(b0), "r"(b1));
}

// ---------------------------------------------------------------------------
// Compensated fp16 GEMM: C = (Ah+Al)[M,K] * (Bh+Bl)[N,K]^T  (3 products)
// 128x128 tile, BK=32, 8 warps (4m x 2n), each warp 32x64.
// ---------------------------------------------------------------------------
template <int KDIM, class Cfg>
__global__ void __launch_bounds__(256) hgemm_comp(Cfg cfg) {
  constexpr int BK = 32;
  constexpr int LDA = 40;  // halves pitch: 80B rows, ldmatrix conflict-free
  __shared__ __half As[2][128 * LDA];
  __shared__ __half Bs[2][128 * LDA];

  const __half* __restrict__ Asrc[2] = {cfg.Ah(), cfg.Al()};
  const __half* __restrict__ Bsrc[2] = {cfg.Bh(), cfg.Bl()};

  const int tid = threadIdx.x;
  const int warp = tid >> 5, lane = tid & 31;
  const int warp_m = warp >> 1, warp_n = warp & 1;
  const int m0 = blockIdx.y * 128;
  const int n0 = blockIdx.x * 128;

  const int lr = tid >> 2;          // 0..63
  const int lc = (tid & 3) << 3;    // 0,8,16,24

  float c[2][8][4];
#pragma unroll
  for (int mi = 0; mi < 2; mi++)
#pragma unroll
    for (int ni = 0; ni < 8; ni++)
#pragma unroll
      for (int j = 0; j < 4; j++) c[mi][ni][j] = 0.f;

  int4 ra[2][2], rb[2][2];
#pragma unroll
  for (int p = 0; p < 2; p++)
#pragma unroll
    for (int h = 0; h < 2; h++) {
      ra[p][h] = *(const int4*)&Asrc[p][(long)(m0 + lr + 64 * h) * KDIM + lc];
      rb[p][h] = *(const int4*)&Bsrc[p][(long)(n0 + lr + 64 * h) * KDIM + lc];
    }

  const uint32_t as_b[2] = {(uint32_t)__cvta_generic_to_shared(As[0]),
                            (uint32_t)__cvta_generic_to_shared(As[1])};
  const uint32_t bs_b[2] = {(uint32_t)__cvta_generic_to_shared(Bs[0]),
                            (uint32_t)__cvta_generic_to_shared(Bs[1])};
  const uint32_t a_off = ((warp_m * 32 + (lane & 15)) * LDA + ((lane >> 4) << 3)) * 2;
  const uint32_t b_off = ((warp_n * 64 + (lane & 15)) * LDA + ((lane >> 4) << 3)) * 2;

#pragma unroll 1
  for (int it = 0; it < KDIM / BK; it++) {
    __syncthreads();
#pragma unroll
    for (int p = 0; p < 2; p++)
#pragma unroll
      for (int h = 0; h < 2; h++) {
        *(int4*)&As[p][(lr + 64 * h) * LDA + lc] = ra[p][h];
        *(int4*)&Bs[p][(lr + 64 * h) * LDA + lc] = rb[p][h];
      }
    __syncthreads();

    if (it + 1 < KDIM / BK) {
      const int k0 = (it + 1) * BK;
#pragma unroll
      for (int p = 0; p < 2; p++)
#pragma unroll
        for (int h = 0; h < 2; h++) {
          ra[p][h] = *(const int4*)&Asrc[p][(long)(m0 + lr + 64 * h) * KDIM + k0 + lc];
          rb[p][h] = *(const int4*)&Bsrc[p][(long)(n0 + lr + 64 * h) * KDIM + k0 + lc];
        }
    }

#pragma unroll
    for (int ks = 0; ks < 2; ks++) {
      uint32_t ah[2][4], al[2][4];
#pragma unroll
      for (int mi = 0; mi < 2; mi++) {
        ldsm_x4(ah[mi][0], ah[mi][1], ah[mi][2], ah[mi][3],
                as_b[0] + a_off + (mi * 16 * LDA + ks * 16) * 2);
        ldsm_x4(al[mi][0], al[mi][1], al[mi][2], al[mi][3],
                as_b[1] + a_off + (mi * 16 * LDA + ks * 16) * 2);
      }
#pragma unroll
      for (int nig = 0; nig < 4; nig++) {
        uint32_t bh0, bh1, bh2, bh3, bl0, bl1, bl2, bl3;
        ldsm_x4(bh0, bh1, bh2, bh3, bs_b[0] + b_off + (nig * 16 * LDA + ks * 16) * 2);
        ldsm_x4(bl0, bl1, bl2, bl3, bs_b[1] + b_off + (nig * 16 * LDA + ks * 16) * 2);
#pragma unroll
        for (int mi = 0; mi < 2; mi++) {
          mma16816(c[mi][2 * nig + 0], ah[mi], bh0, bh2);
          mma16816(c[mi][2 * nig + 1], ah[mi], bh1, bh3);
          mma16816(c[mi][2 * nig + 0], ah[mi], bl0, bl2);
          mma16816(c[mi][2 * nig + 1], ah[mi], bl1, bl3);
          mma16816(c[mi][2 * nig + 0], al[mi], bh0, bh2);
          mma16816(c[mi][2 * nig + 1], al[mi], bh1, bh3);
        }
      }
    }
  }
  cfg.epi(c, m0, n0, warp_m, warp_n, lane);
}

// ---------------- Stage 1: QKV (comp-HMMA) ----------------
struct CfgQKV3 {
  const float* bias;
  __device__ __forceinline__ const __half* Ah() const { return g_hidh; }
  __device__ __forceinline__ const __half* Al() const { return g_hidl; }
  __device__ __forceinline__ const __half* Bh() const { return g_wqh; }
  __device__ __forceinline__ const __half* Bl() const { return g_wql; }
  __device__ __forceinline__ void handle(int m, int n, float v0, float v1) const {
    const int b = m >> 11, s = m & (SEQ - 1);
    const int sec = n / HID;
    const int rem = n - sec * HID;
    const int h = rem >> 6, d = rem & 63;
    const long base = ((long)((b * NH + h) * SEQ + s)) * HDIM + d;
    v0 += bias[n];
    v1 += bias[n + 1];
    if (sec == 0) { v0 *= 0.125f; v1 *= 0.125f; }
    __half h0 = __float2half_rn(v0), h1 = __float2half_rn(v1);
    __half2 hi = __halves2half2(h0, h1);
    if (sec == 2) {
      *(__half2*)&g_vh[base] = hi;
      return;
    }
    __half2 lo = __floats2half2_rn(v0 - __half2float(h0), v1 - __half2float(h1));
    if (sec == 0) {
      *(__half2*)&g_qh[base] = hi;
      *(__half2*)&g_ql[base] = lo;
    } else {
      *(__half2*)&g_kh[base] = hi;
      *(__half2*)&g_kl[base] = lo;
    }
  }
  __device__ __forceinline__ void epi(const float c[2][8][4], int m0, int n0,
                                      int warp_m, int warp_n, int lane) const {
#pragma unroll
    for (int mi = 0; mi < 2; mi++) {
      const int r = m0 + warp_m * 32 + mi * 16 + (lane >> 2);
#pragma unroll
      for (int ni = 0; ni < 8; ni++) {
        const int n = n0 + warp_n * 64 + ni * 8 + 2 * (lane & 3);
        handle(r, n, c[mi][ni][0], c[mi][ni][1]);
        handle(r + 8, n, c[mi][ni][2], c[mi][ni][3]);
      }
    }
  }
};

// ---------------- Stage 5: proj (comp-HMMA) ----------------
struct CfgProj3 {
  const float* bias;
  float* out;
  __device__ __forceinline__ const __half* Ah() const { return g_ctxh; }
  __device__ __forceinline__ const __half* Al() const { return g_ctxl; }
  __device__ __forceinline__ const __half* Bh() const { return g_wph; }
  __device__ __forceinline__ const __half* Bl() const { return g_wpl; }
  __device__ __forceinline__ void epi(const float c[2][8][4], int m0, int n0,
                                      int warp_m, int warp_n, int lane) const {
#pragma unroll
    for (int mi = 0; mi < 2; mi++) {
      const int r = m0 + warp_m * 32 + mi * 16 + (lane >> 2);
#pragma unroll
      for (int ni = 0; ni < 8; ni++) {
        const int n = n0 + warp_n * 64 + ni * 8 + 2 * (lane & 3);
        const float b0 = bias[n], b1 = bias[n + 1];
        *(float2*)&out[(long)r * HID + n] =
            make_float2(c[mi][ni][0] + b0, c[mi][ni][1] + b1);
        *(float2*)&out[(long)(r + 8) * HID + n] =
            make_float2(c[mi][ni][2] + b0, c[mi][ni][3] + b1);
      }
    }
  }
};

// ---------------------------------------------------------------------------
// Stage 2: compensated QK^T per head -> fp32 scores. (R5-proven)
// ---------------------------------------------------------------------------
__global__ void __launch_bounds__(256) qk_comp_kernel() {
  constexpr int LDQ = 72;
  __shared__ __align__(16) __half smem_qk[2 * 128 * LDQ];
  __half* Qs = smem_qk;
  __half* Ks = smem_qk + 128 * LDQ;

  const int head = blockIdx.z;
  const int m0 = blockIdx.y * 128;
  const int n0 = blockIdx.x * 128;
  const long qoff = (long)head * SEQ * HDIM;

  const int tid = threadIdx.x;
  const int warp = tid >> 5, lane = tid & 31;
  const int warp_m = warp >> 1, warp_n = warp & 1;

  const int lrow = tid >> 1;
  const int lcol = (tid & 1) * 32;

  float c[2][8][4];
#pragma unroll
  for (int mi = 0; mi < 2; mi++)
#pragma unroll
    for (int ni = 0; ni < 8; ni++)
#pragma unroll
      for (int j = 0; j < 4; j++) c[mi][ni][j] = 0.f;

  const uint32_t qs_b = (uint32_t)__cvta_generic_to_shared(Qs);
  const uint32_t ks_b = (uint32_t)__cvta_generic_to_shared(Ks);
  const uint32_t a_off = ((warp_m * 32 + (lane & 15)) * LDQ + ((lane >> 4) << 3)) * 2;
  const uint32_t b_off = ((warp_n * 64 + (lane & 15)) * LDQ + ((lane >> 4) << 3)) * 2;

  const __half* qsrc[3] = {g_qh + qoff, g_qh + qoff, g_ql + qoff};
  const __half* ksrc[3] = {g_kh + qoff, g_kl + qoff, g_kh + qoff};

#pragma unroll 1
  for (int ph = 0; ph < 3; ph++) {
    const bool load_q = (ph != 1);
    const __half* Qg = qsrc[ph];
    const __half* Kg = ksrc[ph];
    __syncthreads();
    if (load_q) {
#pragma unroll
      for (int i = 0; i < 4; i++)
        *(int4*)&Qs[lrow * LDQ + lcol + i * 8] =
            *(const int4*)&Qg[(long)(m0 + lrow) * HDIM + lcol + i * 8];
    }
#pragma unroll
    for (int i = 0; i < 4; i++)
      *(int4*)&Ks[lrow * LDQ + lcol + i * 8] =
          *(const int4*)&Kg[(long)(n0 + lrow) * HDIM + lcol + i * 8];
    __syncthreads();

#pragma unroll
    for (int ks = 0; ks < 4; ks++) {
      uint32_t a[2][4];
#pragma unroll
      for (int mi = 0; mi < 2; mi++)
        ldsm_x4(a[mi][0], a[mi][1], a[mi][2], a[mi][3],
                qs_b + a_off + (mi * 16 * LDQ + ks * 16) * 2);
#pragma unroll
      for (int nig = 0; nig < 4; nig++) {
        uint32_t b0, b1, b2, b3;
        ldsm_x4(b0, b1, b2, b3, ks_b + b_off + (nig * 16 * LDQ + ks * 16) * 2);
#pragma unroll
        for (int mi = 0; mi < 2; mi++) {
          mma16816(c[mi][2 * nig + 0], a[mi], b0, b2);
          mma16816(c[mi][2 * nig + 1], a[mi], b1, b3);
        }
      }
    }
  }

  float* C = g_attn + (long long)head * SEQ * SEQ;
#pragma unroll
  for (int mi = 0; mi < 2; mi++) {
    const int r = m0 + warp_m * 32 + mi * 16 + (lane >> 2);
#pragma unroll
    for (int ni = 0; ni < 8; ni++) {
      const int col = n0 + warp_n * 64 + ni * 8 + 2 * (lane & 3);
      *(float2*)&C[(long)r * SEQ + col] = make_float2(c[mi][ni][0], c[mi][ni][1]);
      *(float2*)&C[(long)(r + 8) * SEQ + col] = make_float2(c[mi][ni][2], c[mi][ni][3]);
    }
  }
}

// ---------------------------------------------------------------------------
// Stage 3: exact fp32 k-th largest + masked softmax -> fp16 P. (R5-proven)
// ---------------------------------------------------------------------------
__global__ void __launch_bounds__(256) select_softmax_kernel() {
  const float* row = g_attn + (long long)blockIdx.x * SEQ;
  __half* rowp = g_p + (long long)blockIdx.x * SEQ;

  __shared__ int hist[256];
  __shared__ int scan[256];
  __shared__ float redf[8];
  __shared__ float s_max, s_inv;
  __shared__ int s_bucket, s_r, s_cnt;
  __shared__ unsigned s_thr;
  __shared__ unsigned cand[2048];

  const int tid = threadIdx.x;
  const int warp = tid >> 5, lane = tid & 31;

  float4 va = *(const float4*)&row[tid * 8];
  float4 vb = *(const float4*)&row[tid * 8 + 4];
  float myv[8] = {va.x, va.y, va.z, va.w, vb.x, vb.y, vb.z, vb.w};

  float mx = myv[0];
#pragma unroll
  for (int i = 1; i < 8; i++) mx = fmaxf(mx, myv[i]);
#pragma unroll
  for (int o = 16; o > 0; o >>= 1) mx = fmaxf(mx, __shfl_xor_sync(~0u, mx, o));
  if (lane == 0) redf[warp] = mx;
  hist[tid] = 0;
  __syncthreads();
  if (warp == 0) {
    float m2 = (lane < 8) ? redf[lane] : -3.4e38f;
#pragma unroll
    for (int o = 4; o > 0; o >>= 1) m2 = fmaxf(m2, __shfl_xor_sync(~0u, m2, o));
    if (lane == 0) s_max = m2;
  }

  unsigned key[8];
#pragma unroll
  for (int i = 0; i < 8; i++) {
    int b = __float_as_int(myv[i]);
    key[i] = (unsigned)b ^ ((b < 0) ? 0xFFFFFFFFu : 0x80000000u);
  }

#pragma unroll
  for (int i = 0; i < 8; i++) atomicAdd(&hist[key[i] >> 24], 1);
  __syncthreads();

  scan[tid] = hist[tid];
  __syncthreads();
#pragma unroll
  for (int off = 1; off < 256; off <<= 1) {
    int t = scan[tid] + ((tid + off < 256) ? scan[tid + off] : 0);
    __syncthreads();
    scan[tid] = t;
    __syncthreads();
  }
  if (scan[tid] >= KSEL && (tid == 255 || scan[tid + 1] < KSEL)) {
    s_bucket = tid;
    s_r = KSEL - ((tid == 255) ? 0 : scan[tid + 1]);
    s_cnt = 0;
  }
  __syncthreads();
  const unsigned bucket = (unsigned)s_bucket;

#pragma unroll
  for (int i = 0; i < 8; i++)
    if ((key[i] >> 24) == bucket) cand[atomicAdd(&s_cnt, 1)] = key[i];
  __syncthreads();

  if (warp == 0) {
    const int c = s_cnt;
    int r = s_r;
    unsigned P = bucket << 24;
#pragma unroll 1
    for (int b = 23; b >= 0; b--) {
      const unsigned want = (P | (1u << b)) >> b;
      int cnt = 0;
      for (int i = lane; i < c; i += 32)
        if ((cand[i] >> b) == want) cnt++;
#pragma unroll
      for (int o = 16; o > 0; o >>= 1) cnt += __shfl_xor_sync(~0u, cnt, o);
      if (r <= cnt) P |= 1u << b;
      else r -= cnt;
    }
    if (lane == 0) s_thr = P;
  }
  __syncthreads();
  const unsigned thr = s_thr;
  const float rowmax = s_max;

  const float nm = -rowmax * L2E;
  float myp[8];
  float esum = 0.f;
#pragma unroll
  for (int i = 0; i < 8; i++) {
    float e = (key[i] >= thr) ? fast_exp2(fmaf(myv[i], L2E, nm)) : 0.f;
    myp[i] = e;
    esum += e;
  }
#pragma unroll
  for (int o = 16; o > 0; o >>= 1) esum += __shfl_xor_sync(~0u, esum, o);
  if (lane == 0) redf[warp] = esum;
  __syncthreads();
  if (warp == 0) {
    float z = (lane < 8) ? redf[lane] : 0.f;
#pragma unroll
    for (int o = 4; o > 0; o >>= 1) z += __shfl_xor_sync(~0u, z, o);
    if (lane == 0) s_inv = 1.f / z;
  }
  __syncthreads();
  const float inv = s_inv;

  union { __half2 h[4]; uint4 u; } pk;
#pragma unroll
  for (int i = 0; i < 4; i++)
    pk.h[i] = __floats2half2_rn(myp[2 * i] * inv, myp[2 * i + 1] * inv);
  *(uint4*)&rowp[tid * 8] = pk.u;
}

// ---------------------------------------------------------------------------
// Stage 4: P@V per head with fp16 HMMA; ctx written as fp16 hi+lo.
// ---------------------------------------------------------------------------
__global__ void __launch_bounds__(256) pv_hmma_kernel() {
  constexpr int LDP = 72;
  __shared__ __half Ps[128 * LDP];
  __shared__ __half Vs[64 * LDP];

  const int head = blockIdx.y;
  const int m0 = blockIdx.x * 128;
  const __half* __restrict__ P = g_p + (long long)head * SEQ * SEQ;
  const __half* __restrict__ V = g_vh + (long)head * SEQ * HDIM;

  const int tid = threadIdx.x;
  const int warp = tid >> 5, lane = tid & 31;
  const int wm0 = warp * 16;

  float c[8][4];
#pragma unroll
  for (int i = 0; i < 8; i++)
#pragma unroll
    for (int j = 0; j < 4; j++) c[i][j] = 0.f;

  const int pr = tid >> 3, pc = (tid & 7) << 3;
  const int vr = tid >> 3, vc = (tid & 7) << 3;

  int4 pregs[4], vregs[2];
#pragma unroll
  for (int l = 0; l < 4; l++)
    pregs[l] = *(const int4*)&P[(long)(m0 + pr + 32 * l) * SEQ + pc];
#pragma unroll
  for (int l = 0; l < 2; l++)
    vregs[l] = *(const int4*)&V[(long)(vr + 32 * l) * HDIM + vc];

  const uint32_t ps_base = (uint32_t)__cvta_generic_to_shared(Ps);
  const uint32_t vs_base = (uint32_t)__cvta_generic_to_shared(Vs);
  const uint32_t a_addr0 =
      ps_base + ((wm0 + (lane & 15)) * LDP + ((lane >> 4) << 3)) * 2;
  const uint32_t b_row = (lane & 7) + (lane & 8);
  const uint32_t b_addr0 = vs_base + (b_row * LDP + ((lane & 16) >> 1)) * 2;

#pragma unroll 1
  for (int it = 0; it < SEQ / 64; it++) {
    __syncthreads();
#pragma unroll
    for (int l = 0; l < 4; l++)
      *(int4*)&Ps[(pr + 32 * l) * LDP + pc] = pregs[l];
#pragma unroll
    for (int l = 0; l < 2; l++)
      *(int4*)&Vs[(vr + 32 * l) * LDP + vc] = vregs[l];
    __syncthreads();

    if (it + 1 < SEQ / 64) {
      int k0n = (it + 1) * 64;
#pragma unroll
      for (int l = 0; l < 4; l++)
        pregs[l] = *(const int4*)&P[(long)(m0 + pr + 32 * l) * SEQ + k0n + pc];
#pragma unroll
      for (int l = 0; l < 2; l++)
        vregs[l] = *(const int4*)&V[(long)(k0n + vr + 32 * l) * HDIM + vc];
    }

#pragma unroll
    for (int ks = 0; ks < 4; ks++) {
      uint32_t a[4];
      ldsm_x4(a[0], a[1], a[2], a[3], a_addr0 + ks * 16 * 2);
#pragma unroll
      for (int g = 0; g < 4; g++) {
        uint32_t b0, b1, b2, b3;
        ldsm_x4_t(b0, b1, b2, b3, b_addr0 + (ks * 16 * LDP + g * 16) * 2);
        mma16816(c[2 * g + 0], a, b0, b1);
        mma16816(c[2 * g + 1], a, b2, b3);
      }
    }
  }

  // epilogue -> ctx fp16 hi+lo [B,S,H]
  const int b = head / NH, h = head - b * NH;
  const int r0 = lane >> 2, col0 = (lane & 3) * 2;
  const long rowbase0 = (long)(b * SEQ + m0 + wm0 + r0) * HID + h * HDIM;
  const long rowbase1 = rowbase0 + 8L * HID;
#pragma unroll
  for (int nt = 0; nt < 8; nt++) {
    const int n = nt * 8 + col0;
    {
      float v0 = c[nt][0], v1 = c[nt][1];
      __half h0 = __float2half_rn(v0), h1 = __float2half_rn(v1);
      *(__half2*)&g_ctxh[rowbase0 + n] = __halves2half2(h0, h1);
      *(__half2*)&g_ctxl[rowbase0 + n] =
          __floats2half2_rn(v0 - __half2float(h0), v1 - __half2float(h1));
    }
    {
      float v0 = c[nt][2], v1 = c[nt][3];
      __half h0 = __float2half_rn(v0), h1 = __float2half_rn(v1);
      *(__half2*)&g_ctxh[rowbase1 + n] = __halves2half2(h0, h1);
      *(__half2*)&g_ctxl[rowbase1 + n] =
          __floats2half2_rn(v0 - __half2float(h0), v1 - __half2float(h1));
    }
  }
}

// ---------------------------------------------------------------------------
extern "C" void kernel_launch(void* const* d_in, const int* in_sizes, int n_in,
                              void* d_out, int out_size) {
  const float* hidden = (const float*)d_in[0];
  const float* qkv_w  = (const float*)d_in[1];
  const float* qkv_b  = (const float*)d_in[2];
  const float* proj_w = (const float*)d_in[3];
  const float* proj_b = (const float*)d_in[4];
  float* out = (float*)d_out;

  // 0) operand splits
  {
    __half *hidh, *hidl, *wqh, *wql, *wph, *wpl;
    cudaGetSymbolAddress((void**)&hidh, g_hidh);
    cudaGetSymbolAddress((void**)&hidl, g_hidl);
    cudaGetSymbolAddress((void**)&wqh, g_wqh);
    cudaGetSymbolAddress((void**)&wql, g_wql);
    cudaGetSymbolAddress((void**)&wph, g_wph);
    cudaGetSymbolAddress((void**)&wpl, g_wpl);
    int n1 = BATCH * SEQ * HID / 4;
    int n2 = 3 * HID * HID / 4;
    int n3 = HID * HID / 4;
    split_kernel<<<(n1 + 255) / 256, 256>>>(hidden, hidh, hidl, n1);
    split_kernel<<<(n2 + 255) / 256, 256>>>(qkv_w, wqh, wql, n2);
    split_kernel<<<(n3 + 255) / 256, 256>>>(proj_w, wph, wpl, n3);
  }

  // 1) QKV comp-HMMA: M=4096, N=2304, K=768
  hgemm_comp<HID><<<dim3((3 * HID) / 128, (BATCH * SEQ) / 128), 256>>>(
      CfgQKV3{qkv_b});

  // 2) QK^T comp-HMMA per head
  qk_comp_kernel<<<dim3(SEQ / 128, SEQ / 128, HEADS), 256>>>();

  // 3) exact select + softmax
  select_softmax_kernel<<<dim3(HEADS * SEQ), 256>>>();

  // 4) PV HMMA
  pv_hmma_kernel<<<dim3(SEQ / 128, HEADS), 256>>>();

  // 5) proj comp-HMMA: M=4096, N=768, K=768
  hgemm_comp<HID><<<dim3(HID / 128, (BATCH * SEQ) / 128), 256>>>(
      CfgProj3{proj_b, out});
}